// round 8
// baseline (speedup 1.0000x reference)
#include <cuda_runtime.h>
#include <cuda_fp16.h>
#include <cstdint>
#include <cstddef>

#define TT    8192
#define DIN   4096
#define DOUT  4096
#define NE    8
#define NR    16
#define NCAT  128      // 8 experts * rank 16
#define BM    128

using h16 = __half;

// ---------------- device scratch (allocation-free rule) ----------------
__device__ __align__(1024) h16  g_xh[(size_t)TT * DIN];
__device__ __align__(1024) h16  g_xl[(size_t)TT * DIN];
__device__ __align__(1024) h16  g_wh[(size_t)DOUT * DIN];
__device__ __align__(1024) h16  g_ah[(size_t)NCAT * DIN];
__device__ __align__(1024) h16  g_bh[(size_t)DOUT * NCAT];
__device__ __align__(1024) h16  g_ch[(size_t)TT * NCAT];
__device__ __align__(1024) float g_H[(size_t)TT * NCAT];
__device__ __align__(1024) float g_lg[(size_t)TT * NE];

// ---------------- helpers ----------------
__device__ __forceinline__ uint32_t smem_u32(const void* p) {
    uint32_t a;
    asm("{ .reg .u64 t; cvta.to.shared.u64 t, %1; cvt.u32.u64 %0, t; }" : "=r"(a) : "l"(p));
    return a;
}
#define SWZ(o) ((o) ^ (((o) >> 3) & 0x70))

__device__ __forceinline__ void cp16(uint32_t dst, const void* src) {
    asm volatile("cp.async.cg.shared.global [%0], [%1], 16;" :: "r"(dst), "l"(src) : "memory");
}
__device__ __forceinline__ void cp_commit() {
    asm volatile("cp.async.commit_group;" ::: "memory");
}
template <int N>
__device__ __forceinline__ void cp_wait() {
    asm volatile("cp.async.wait_group %0;" :: "n"(N) : "memory");
}
__device__ __forceinline__ void ldm4(uint32_t& r0, uint32_t& r1, uint32_t& r2, uint32_t& r3,
                                     uint32_t addr) {
    asm volatile("ldmatrix.sync.aligned.m8n8.x4.shared.b16 {%0,%1,%2,%3}, [%4];"
                 : "=r"(r0), "=r"(r1), "=r"(r2), "=r"(r3) : "r"(addr));
}
__device__ __forceinline__ void mma16(float* c, const uint32_t* a, const uint32_t* b) {
    asm volatile(
        "mma.sync.aligned.m16n8k16.row.col.f32.f16.f16.f32 "
        "{%0,%1,%2,%3}, {%4,%5,%6,%7}, {%8,%9}, {%0,%1,%2,%3};"
        : "+f"(c[0]), "+f"(c[1]), "+f"(c[2]), "+f"(c[3])
        : "r"(a[0]), "r"(a[1]), "r"(a[2]), "r"(a[3]), "r"(b[0]), "r"(b[1]));
}

// ---------------- prep kernels ----------------
__global__ void tohalf_k(const float* __restrict__ in, h16* __restrict__ out, int n4) {
    int i = blockIdx.x * blockDim.x + threadIdx.x;
    if (i >= n4) return;
    float4 v = ((const float4*)in)[i];
    h16 o[4] = {__float2half_rn(v.x), __float2half_rn(v.y),
                __float2half_rn(v.z), __float2half_rn(v.w)};
    *(uint2*)&out[i * 4] = *(uint2*)o;
}

// Bcat[n, e*16+r] = B[e, n, r] (fp16)
__global__ void bcat_k(const float* __restrict__ B, h16* __restrict__ bh) {
    int i = blockIdx.x * blockDim.x + threadIdx.x;
    if (i >= DOUT * NCAT) return;
    int n = i / NCAT, c = i % NCAT;
    int e = c >> 4, r = c & 15;
    bh[i] = __float2half_rn(B[((size_t)e * DOUT + n) * NR + r]);
}

// fused: x -> fp16 hi/lo split + fp32 router logits (W_router cached in smem)
// fp32 logits are load-bearing: a single top-2 tie flip costs ~9e-4 global rel err.
__global__ __launch_bounds__(256, 1) void router_splitx_k(
    const float* __restrict__ x, const float* __restrict__ wr,
    float* __restrict__ logits, h16* __restrict__ xh, h16* __restrict__ xl) {
    extern __shared__ float s_wr[];            // 8*4096 f32 = 128 KB
    __shared__ float s_red[8][9];
    int tid = threadIdx.x, lane = tid & 31, wid = tid >> 5;
    for (int i = tid; i < NE * (DIN / 4); i += 256)
        ((float4*)s_wr)[i] = ((const float4*)wr)[i];
    __syncthreads();
    for (int t = blockIdx.x; t < TT; t += gridDim.x) {
        float acc[NE];
        #pragma unroll
        for (int e = 0; e < NE; e++) acc[e] = 0.f;
        const float4* xr = (const float4*)(x + (size_t)t * DIN);
        for (int i = tid; i < DIN / 4; i += 256) {
            float4 xv = xr[i];
            float vv[4] = {xv.x, xv.y, xv.z, xv.w};
            h16 hh[4], ll[4];
            #pragma unroll
            for (int j = 0; j < 4; j++) {
                hh[j] = __float2half_rn(vv[j]);
                ll[j] = __float2half_rn(vv[j] - __half2float(hh[j]));
            }
            *(uint2*)&xh[(size_t)t * DIN + i * 4] = *(uint2*)hh;
            *(uint2*)&xl[(size_t)t * DIN + i * 4] = *(uint2*)ll;
            #pragma unroll
            for (int e = 0; e < NE; e++) {
                float4 wv = ((const float4*)s_wr)[e * (DIN / 4) + i];
                acc[e] += xv.x * wv.x + xv.y * wv.y + xv.z * wv.z + xv.w * wv.w;
            }
        }
        #pragma unroll
        for (int e = 0; e < NE; e++)
            #pragma unroll
            for (int o = 16; o > 0; o >>= 1)
                acc[e] += __shfl_down_sync(0xFFFFFFFFu, acc[e], o);
        if (lane == 0)
            #pragma unroll
            for (int e = 0; e < NE; e++) s_red[wid][e] = acc[e];
        __syncthreads();
        if (tid < NE) {
            float s = 0.f;
            #pragma unroll
            for (int w = 0; w < 8; w++) s += s_red[w][tid];
            logits[(size_t)t * NE + tid] = s;
        }
        __syncthreads();
    }
}

// top-2 + softmax -> C[t, e*16+r] = 2*w_e*H[t, e*16+r] (fp16); others zero
__global__ void combine_k(const float* __restrict__ logits, const float* __restrict__ H,
                          h16* __restrict__ ch) {
    int t = blockIdx.x, tid = threadIdx.x;
    __shared__ float sw[2];
    __shared__ int se[2];
    if (tid == 0) {
        float l[NE];
        #pragma unroll
        for (int e = 0; e < NE; e++) l[e] = logits[(size_t)t * NE + e];
        int i1 = 0;
        #pragma unroll
        for (int e = 1; e < NE; e++) if (l[e] > l[i1]) i1 = e;   // ties: lowest idx (matches lax.top_k)
        int i2 = (i1 == 0) ? 1 : 0;
        #pragma unroll
        for (int e = 0; e < NE; e++) if (e != i1 && l[e] > l[i2]) i2 = e;
        float w1 = 1.f / (1.f + expf(l[i2] - l[i1]));
        se[0] = i1; se[1] = i2;
        sw[0] = 2.0f * w1;                     // SCALING = 2 folded in
        sw[1] = 2.0f * (1.f - w1);
    }
    uint32_t* chp = (uint32_t*)(ch + (size_t)t * NCAT);
    chp[tid] = 0u; chp[tid + 32] = 0u;         // 128 halfs = 64 u32
    __syncthreads();
    int k = tid >> 4, r = tid & 15;
    int e = se[k];
    float c = sw[k] * H[(size_t)t * NCAT + e * 16 + r];
    ch[(size_t)t * NCAT + e * 16 + r] = __float2half_rn(c);
}

// ---- mma.sync GEMM, interleaved split: out = (Axh+Axl)@Bw^T (+ AC@Bb^T) + bias ----
// Stage = {A_hi 16K, A_lo 16K, B}. Both passes share one B load per K-tile
// (33% less gmem traffic vs sequential passes). 3-stage cp.async, prefetch 2.
template <int BN>
__global__ __launch_bounds__(512, 1) void gemm_mma(
    const h16* __restrict__ Axh, const h16* __restrict__ Axl, const h16* __restrict__ Bw,
    const h16* __restrict__ AC, const h16* __restrict__ Bb,
    int KI, int NITER, int LDA,
    float* __restrict__ out, const float* __restrict__ bias, int ldo) {
    constexpr int NT = BN / 32;              // n8 tiles per warp
    constexpr int NTT = NT / 2;              // n16 ldmatrix groups per warp
    constexpr int A_SZ = BM * 128;           // one A tile (16 KB)
    constexpr int STAGE = 2 * A_SZ + BN * 128;
    constexpr int ACH = BM * 8;              // 16B chunks per A tile
    constexpr int TCH = (2 * BM + BN) * 8;   // total chunks per stage
    constexpr int CH_IT = TCH / 512;

    extern __shared__ char dsmem[];
    uint32_t tiles = (smem_u32(dsmem) + 1023u) & ~1023u;

    int tid = threadIdx.x, lane = tid & 31, wid = tid >> 5;
    int wm = wid >> 2, wn = wid & 3;         // 4x4 warp grid
    const int n0 = blockIdx.x * BN;
    const int m0 = blockIdx.y * BM;
    const int lrow = (lane & 7) + 8 * ((lane >> 3) & 1);
    const int lcol = 8 * (lane >> 4);

    float acc[2][NT][4];
    #pragma unroll
    for (int mt = 0; mt < 2; mt++)
        #pragma unroll
        for (int nt = 0; nt < NT; nt++)
            #pragma unroll
            for (int j = 0; j < 4; j++) acc[mt][nt][j] = 0.f;

    // producer: one K-tile = A_hi + A_lo + B (ext iters: A_hi only + B)
    auto load_stage = [&](int L, int slot) {
        bool ext = (L >= KI);
        const h16* gah = ext ? AC : Axh;
        const h16* gb  = ext ? Bb : Bw;
        int k0  = (ext ? L - KI : L) * 64;
        int lda = ext ? NCAT : LDA;
        uint32_t sAh = tiles + slot * STAGE;
        uint32_t sAl = sAh + A_SZ;
        uint32_t sB  = sAh + 2 * A_SZ;
        #pragma unroll
        for (int j = 0; j < CH_IT; j++) {
            int hch = tid + j * 512;
            if (hch < ACH) {
                int r = hch >> 3, c = hch & 7;
                cp16(sAh + SWZ(r * 128 + c * 16), gah + (size_t)(m0 + r) * lda + k0 + c * 8);
            } else if (hch < 2 * ACH) {
                if (!ext) {
                    int h2 = hch - ACH;
                    int r = h2 >> 3, c = h2 & 7;
                    cp16(sAl + SWZ(r * 128 + c * 16), Axl + (size_t)(m0 + r) * LDA + k0 + c * 8);
                }
            } else {
                int h2 = hch - 2 * ACH;
                int r = h2 >> 3, c = h2 & 7;
                cp16(sB + SWZ(r * 128 + c * 16), gb + (size_t)(n0 + r) * lda + k0 + c * 8);
            }
        }
    };

    load_stage(0, 0); cp_commit();
    load_stage(1, 1); cp_commit();

    for (int i = 0; i < NITER; i++) {
        int s = i % 3;
        bool haslo = (i < KI);
        cp_wait<1>();
        __syncthreads();       // bounds warp skew; write slot (i+2)%3 == (i-1)%3 is safe
        uint32_t sAh = tiles + s * STAGE;
        uint32_t sAl = sAh + A_SZ;
        uint32_t sB  = sAh + 2 * A_SZ;
        #pragma unroll
        for (int ks = 0; ks < 4; ks++) {
            int k0 = ks * 16;
            uint32_t ah[2][4], al[2][4], bf[NT][2];
            uint32_t aoff = SWZ((wm * 32 + lrow) * 128 + (k0 + lcol) * 2);
            uint32_t aoff2 = SWZ((wm * 32 + 16 + lrow) * 128 + (k0 + lcol) * 2);
            ldm4(ah[0][0], ah[0][1], ah[0][2], ah[0][3], sAh + aoff);
            ldm4(ah[1][0], ah[1][1], ah[1][2], ah[1][3], sAh + aoff2);
            if (haslo) {
                ldm4(al[0][0], al[0][1], al[0][2], al[0][3], sAl + aoff);
                ldm4(al[1][0], al[1][1], al[1][2], al[1][3], sAl + aoff2);
            }
            #pragma unroll
            for (int tt = 0; tt < NTT; tt++) {
                uint32_t r0, r1, r2, r3;
                uint32_t addr = sB + SWZ((wn * (BN / 4) + tt * 16 + lrow) * 128 + (k0 + lcol) * 2);
                ldm4(r0, r1, r2, r3, addr);
                bf[2 * tt][0] = r0; bf[2 * tt][1] = r2;         // n tile 2tt:   k0-7, k8-15
                bf[2 * tt + 1][0] = r1; bf[2 * tt + 1][1] = r3; // n tile 2tt+1
            }
            #pragma unroll
            for (int mt = 0; mt < 2; mt++)
                #pragma unroll
                for (int nt = 0; nt < NT; nt++)
                    mma16(acc[mt][nt], ah[mt], bf[nt]);
            if (haslo)
                #pragma unroll
                for (int mt = 0; mt < 2; mt++)
                    #pragma unroll
                    for (int nt = 0; nt < NT; nt++)
                        mma16(acc[mt][nt], al[mt], bf[nt]);
        }
        int Ln = i + 2;
        if (Ln < NITER) load_stage(Ln, Ln % 3);
        cp_commit();           // commit every iter to keep wait_group counting exact
    }

    // epilogue
    #pragma unroll
    for (int mt = 0; mt < 2; mt++) {
        int r = m0 + wm * 32 + mt * 16 + (lane >> 2);
        #pragma unroll
        for (int nt = 0; nt < NT; nt++) {
            int cc = n0 + wn * (BN / 4) + nt * 8 + 2 * (lane & 3);
            float b0 = 0.f, b1 = 0.f;
            if (bias) { b0 = bias[cc]; b1 = bias[cc + 1]; }
            float2 v0 = make_float2(acc[mt][nt][0] + b0, acc[mt][nt][1] + b1);
            float2 v1 = make_float2(acc[mt][nt][2] + b0, acc[mt][nt][3] + b1);
            *(float2*)(out + (size_t)r * ldo + cc) = v0;
            *(float2*)(out + (size_t)(r + 8) * ldo + cc) = v1;
        }
    }
}

// ---------------- host ----------------
extern "C" void kernel_launch(void* const* d_in, const int* in_sizes, int n_in,
                              void* d_out, int out_size) {
    const float* x  = (const float*)d_in[0];
    const float* Wb = (const float*)d_in[1];
    const float* bb = (const float*)d_in[2];
    const float* Wr = (const float*)d_in[3];
    const float* A  = (const float*)d_in[4];
    const float* B  = (const float*)d_in[5];
    float* out = (float*)d_out;

    void *p_xh, *p_xl, *p_wh, *p_ah, *p_bh, *p_ch, *p_H, *p_lg;
    cudaGetSymbolAddress(&p_xh, g_xh); cudaGetSymbolAddress(&p_xl, g_xl);
    cudaGetSymbolAddress(&p_wh, g_wh); cudaGetSymbolAddress(&p_ah, g_ah);
    cudaGetSymbolAddress(&p_bh, g_bh); cudaGetSymbolAddress(&p_ch, g_ch);
    cudaGetSymbolAddress(&p_H, g_H);   cudaGetSymbolAddress(&p_lg, g_lg);

    // prep: converts + fused router/x-split
    tohalf_k<<<(DOUT * DIN / 4) / 256, 256>>>(Wb, (h16*)p_wh, DOUT * DIN / 4);
    tohalf_k<<<(NCAT * DIN / 4) / 256, 256>>>(A, (h16*)p_ah, NCAT * DIN / 4);  // A is [128,4096]
    bcat_k<<<(DOUT * NCAT) / 256, 256>>>(B, (h16*)p_bh);
    cudaFuncSetAttribute(router_splitx_k, cudaFuncAttributeMaxDynamicSharedMemorySize, 131072);
    router_splitx_k<<<148, 256, 131072>>>(x, Wr, (float*)p_lg, (h16*)p_xh, (h16*)p_xl);

    // H = x @ Acat^T (interleaved 2-pass fp16). BN=64 -> 128 CTAs.
    constexpr int SM_H = 3 * (2 * BM + 64) * 128 + 1024;
    cudaFuncSetAttribute(gemm_mma<64>, cudaFuncAttributeMaxDynamicSharedMemorySize, SM_H);
    gemm_mma<64><<<dim3(2, TT / BM), 512, SM_H>>>(
        (const h16*)p_xh, (const h16*)p_xl, (const h16*)p_ah,
        (const h16*)nullptr, (const h16*)nullptr,
        DIN / 64, DIN / 64, DIN, (float*)p_H, nullptr, NCAT);

    combine_k<<<TT, 32>>>((float*)p_lg, (float*)p_H, (h16*)p_ch);

    // out = x @ W^T + C @ Bcat^T + bias  (LoRA rides as 2 hi-only iters)
    constexpr int SM_M = 3 * (2 * BM + 256) * 128 + 1024;
    cudaFuncSetAttribute(gemm_mma<256>, cudaFuncAttributeMaxDynamicSharedMemorySize, SM_M);
    gemm_mma<256><<<dim3(DOUT / 256, TT / BM), 512, SM_M>>>(
        (const h16*)p_xh, (const h16*)p_xl, (const h16*)p_wh,
        (const h16*)p_ch, (const h16*)p_bh,
        DIN / 64, DIN / 64 + 2, DIN, out, bb, DOUT);
}

// round 15
// speedup vs baseline: 1.9445x; 1.9445x over previous
#include <cuda_runtime.h>
#include <cuda_fp16.h>
#include <cstdint>
#include <cstddef>

#define TT    8192
#define DIN   4096
#define DOUT  4096
#define NE    8
#define NR    16
#define NCAT  128      // 8 experts * rank 16
#define BM    128

using h16 = __half;

// ---------------- device scratch (allocation-free rule) ----------------
__device__ __align__(1024) h16  g_xh[(size_t)TT * DIN];
__device__ __align__(1024) h16  g_wh[(size_t)DOUT * DIN];
__device__ __align__(1024) h16  g_ah[(size_t)NCAT * DIN];
__device__ __align__(1024) h16  g_bh[(size_t)DOUT * NCAT];
__device__ __align__(1024) h16  g_ch[(size_t)TT * NCAT];
__device__ __align__(1024) float g_H[(size_t)TT * NCAT];
__device__ __align__(1024) float g_lg[(size_t)TT * NE];

// ---------------- helpers ----------------
__device__ __forceinline__ uint32_t smem_u32(const void* p) {
    uint32_t a;
    asm("{ .reg .u64 t; cvta.to.shared.u64 t, %1; cvt.u32.u64 %0, t; }" : "=r"(a) : "l"(p));
    return a;
}
#define SWZ(o) ((o) ^ (((o) >> 3) & 0x70))

__device__ __forceinline__ void cp16(uint32_t dst, const void* src) {
    asm volatile("cp.async.cg.shared.global [%0], [%1], 16;" :: "r"(dst), "l"(src) : "memory");
}
__device__ __forceinline__ void cp_commit() {
    asm volatile("cp.async.commit_group;" ::: "memory");
}
template <int N>
__device__ __forceinline__ void cp_wait() {
    asm volatile("cp.async.wait_group %0;" :: "n"(N) : "memory");
}
__device__ __forceinline__ void ldm4(uint32_t& r0, uint32_t& r1, uint32_t& r2, uint32_t& r3,
                                     uint32_t addr) {
    asm volatile("ldmatrix.sync.aligned.m8n8.x4.shared.b16 {%0,%1,%2,%3}, [%4];"
                 : "=r"(r0), "=r"(r1), "=r"(r2), "=r"(r3) : "r"(addr));
}
__device__ __forceinline__ void mma16(float* c, const uint32_t* a, const uint32_t* b) {
    asm volatile(
        "mma.sync.aligned.m16n8k16.row.col.f32.f16.f16.f32 "
        "{%0,%1,%2,%3}, {%4,%5,%6,%7}, {%8,%9}, {%0,%1,%2,%3};"
        : "+f"(c[0]), "+f"(c[1]), "+f"(c[2]), "+f"(c[3])
        : "r"(a[0]), "r"(a[1]), "r"(a[2]), "r"(a[3]), "r"(b[0]), "r"(b[1]));
}

// ---------------- prep kernels ----------------
__global__ void tohalf_k(const float* __restrict__ in, h16* __restrict__ out, int n4) {
    int i = blockIdx.x * blockDim.x + threadIdx.x;
    if (i >= n4) return;
    float4 v = ((const float4*)in)[i];
    h16 o[4] = {__float2half_rn(v.x), __float2half_rn(v.y),
                __float2half_rn(v.z), __float2half_rn(v.w)};
    *(uint2*)&out[i * 4] = *(uint2*)o;
}

// Bcat[n, e*16+r] = B[e, n, r] (fp16)
__global__ void bcat_k(const float* __restrict__ B, h16* __restrict__ bh) {
    int i = blockIdx.x * blockDim.x + threadIdx.x;
    if (i >= DOUT * NCAT) return;
    int n = i / NCAT, c = i % NCAT;
    int e = c >> 4, r = c & 15;
    bh[i] = __float2half_rn(B[((size_t)e * DOUT + n) * NR + r]);
}

// Warp-per-token: x -> fp16 + fp32 router logits. 1024 thr (32 warps, occ 50%),
// W_router cached in 128KB smem, zero block syncs in the token work (shfl only).
// fp32 logits are load-bearing: one top-2 flip costs ~9e-4 global rel err.
__global__ __launch_bounds__(1024, 1) void router_splitx_k(
    const float* __restrict__ x, const float* __restrict__ wr,
    float* __restrict__ logits, h16* __restrict__ xh) {
    extern __shared__ float s_wr[];            // 8*4096 f32 = 128 KB
    int tid = threadIdx.x, lane = tid & 31, wid = tid >> 5;
    for (int i = tid; i < NE * (DIN / 4); i += 1024)
        ((float4*)s_wr)[i] = ((const float4*)wr)[i];
    __syncthreads();

    int t = blockIdx.x * 32 + wid;             // grid 256 x 32 warps = 8192 tokens
    const float4* xr = (const float4*)(x + (size_t)t * DIN);
    float acc[NE];
    #pragma unroll
    for (int e = 0; e < NE; e++) acc[e] = 0.f;
    #pragma unroll 4
    for (int c = 0; c < 32; c++) {
        int idx = c * 32 + lane;               // float4 index within the row
        float4 xv = xr[idx];
        h16 hh[4] = {__float2half_rn(xv.x), __float2half_rn(xv.y),
                     __float2half_rn(xv.z), __float2half_rn(xv.w)};
        *(uint2*)&xh[(size_t)t * DIN + idx * 4] = *(uint2*)hh;
        #pragma unroll
        for (int e = 0; e < NE; e++) {
            float4 wv = ((const float4*)s_wr)[e * (DIN / 4) + idx];
            acc[e] += xv.x * wv.x + xv.y * wv.y + xv.z * wv.z + xv.w * wv.w;
        }
    }
    #pragma unroll
    for (int e = 0; e < NE; e++)
        #pragma unroll
        for (int o = 16; o > 0; o >>= 1)
            acc[e] += __shfl_down_sync(0xFFFFFFFFu, acc[e], o);
    if (lane == 0)
        #pragma unroll
        for (int e = 0; e < NE; e++) logits[(size_t)t * NE + e] = acc[e];
}

// top-2 + softmax -> C[t, e*16+r] = 2*w_e*H[t, e*16+r] (fp16); others zero
__global__ void combine_k(const float* __restrict__ logits, const float* __restrict__ H,
                          h16* __restrict__ ch) {
    int t = blockIdx.x, tid = threadIdx.x;
    __shared__ float sw[2];
    __shared__ int se[2];
    if (tid == 0) {
        float l[NE];
        #pragma unroll
        for (int e = 0; e < NE; e++) l[e] = logits[(size_t)t * NE + e];
        int i1 = 0;
        #pragma unroll
        for (int e = 1; e < NE; e++) if (l[e] > l[i1]) i1 = e;   // ties: lowest idx (matches lax.top_k)
        int i2 = (i1 == 0) ? 1 : 0;
        #pragma unroll
        for (int e = 0; e < NE; e++) if (e != i1 && l[e] > l[i2]) i2 = e;
        float w1 = 1.f / (1.f + expf(l[i2] - l[i1]));
        se[0] = i1; se[1] = i2;
        sw[0] = 2.0f * w1;                     // SCALING = 2 folded in
        sw[1] = 2.0f * (1.f - w1);
    }
    uint32_t* chp = (uint32_t*)(ch + (size_t)t * NCAT);
    chp[tid] = 0u; chp[tid + 32] = 0u;         // 128 halfs = 64 u32
    __syncthreads();
    int k = tid >> 4, r = tid & 15;
    int e = se[k];
    float c = sw[k] * H[(size_t)t * NCAT + e * 16 + r];
    ch[(size_t)t * NCAT + e * 16 + r] = __float2half_rn(c);
}

// ---- mma.sync GEMM (single-pass fp16): out = Ax@Bw^T (+ AC@Bb^T) + bias ----
// BK=64, 4-stage cp.async pipeline (prefetch 3), SW128-style XOR swizzle, 512 thr.
template <int BN>
__global__ __launch_bounds__(512, 1) void gemm_mma(
    const h16* __restrict__ Ax, const h16* __restrict__ Bw,
    const h16* __restrict__ AC, const h16* __restrict__ Bb,
    int KI, int NITER, int LDA,
    float* __restrict__ out, const float* __restrict__ bias, int ldo) {
    constexpr int NT = BN / 32;              // n8 tiles per warp
    constexpr int NTT = NT / 2;              // n16 ldmatrix groups per warp
    constexpr int STAGE = (BM + BN) * 128;   // bytes per stage
    constexpr int ACH = BM * 8;              // 16B chunks in A tile
    constexpr int CH_IT = (BM + BN) * 8 / 512;

    extern __shared__ char dsmem[];
    uint32_t tiles = (smem_u32(dsmem) + 1023u) & ~1023u;

    int tid = threadIdx.x, lane = tid & 31, wid = tid >> 5;
    int wm = wid >> 2, wn = wid & 3;         // 4x4 warp grid
    const int n0 = blockIdx.x * BN;
    const int m0 = blockIdx.y * BM;
    const int lrow = (lane & 7) + 8 * ((lane >> 3) & 1);
    const int lcol = 8 * (lane >> 4);

    float acc[2][NT][4];
    #pragma unroll
    for (int mt = 0; mt < 2; mt++)
        #pragma unroll
        for (int nt = 0; nt < NT; nt++)
            #pragma unroll
            for (int j = 0; j < 4; j++) acc[mt][nt][j] = 0.f;

    auto load_stage = [&](int L, int slot) {
        bool ext = (L >= KI);
        const h16* ga = ext ? AC : Ax;
        const h16* gb = ext ? Bb : Bw;
        int k0  = (ext ? L - KI : L) * 64;
        int lda = ext ? NCAT : LDA;
        uint32_t sA = tiles + slot * STAGE;
        uint32_t sB = sA + BM * 128;
        #pragma unroll
        for (int j = 0; j < CH_IT; j++) {
            int hch = tid + j * 512;
            if (hch < ACH) {
                int r = hch >> 3, c = hch & 7;
                cp16(sA + SWZ(r * 128 + c * 16), ga + (size_t)(m0 + r) * lda + k0 + c * 8);
            } else {
                int h2 = hch - ACH;
                int r = h2 >> 3, c = h2 & 7;
                cp16(sB + SWZ(r * 128 + c * 16), gb + (size_t)(n0 + r) * lda + k0 + c * 8);
            }
        }
    };

    load_stage(0, 0); cp_commit();
    load_stage(1, 1); cp_commit();
    load_stage(2, 2); cp_commit();

    for (int i = 0; i < NITER; i++) {
        int s = i & 3;
        cp_wait<2>();
        __syncthreads();       // bounds warp skew; write slot (i+3)%4 never collides
        uint32_t sA = tiles + s * STAGE;
        uint32_t sB = sA + BM * 128;
        #pragma unroll
        for (int ks = 0; ks < 4; ks++) {
            int k0 = ks * 16;
            uint32_t af[2][4], bf[NT][2];
            #pragma unroll
            for (int mt = 0; mt < 2; mt++) {
                uint32_t addr = sA + SWZ((wm * 32 + mt * 16 + lrow) * 128 + (k0 + lcol) * 2);
                ldm4(af[mt][0], af[mt][1], af[mt][2], af[mt][3], addr);
            }
            #pragma unroll
            for (int tt = 0; tt < NTT; tt++) {
                uint32_t r0, r1, r2, r3;
                uint32_t addr = sB + SWZ((wn * (BN / 4) + tt * 16 + lrow) * 128 + (k0 + lcol) * 2);
                ldm4(r0, r1, r2, r3, addr);
                bf[2 * tt][0] = r0; bf[2 * tt][1] = r2;         // n tile 2tt:   k0-7, k8-15
                bf[2 * tt + 1][0] = r1; bf[2 * tt + 1][1] = r3; // n tile 2tt+1
            }
            #pragma unroll
            for (int mt = 0; mt < 2; mt++)
                #pragma unroll
                for (int nt = 0; nt < NT; nt++)
                    mma16(acc[mt][nt], af[mt], bf[nt]);
        }
        int Ln = i + 3;
        if (Ln < NITER) load_stage(Ln, Ln & 3);
        cp_commit();           // commit every iter keeps wait_group counting exact
    }

    // epilogue
    #pragma unroll
    for (int mt = 0; mt < 2; mt++) {
        int r = m0 + wm * 32 + mt * 16 + (lane >> 2);
        #pragma unroll
        for (int nt = 0; nt < NT; nt++) {
            int cc = n0 + wn * (BN / 4) + nt * 8 + 2 * (lane & 3);
            float b0 = 0.f, b1 = 0.f;
            if (bias) { b0 = bias[cc]; b1 = bias[cc + 1]; }
            float2 v0 = make_float2(acc[mt][nt][0] + b0, acc[mt][nt][1] + b1);
            float2 v1 = make_float2(acc[mt][nt][2] + b0, acc[mt][nt][3] + b1);
            *(float2*)(out + (size_t)r * ldo + cc) = v0;
            *(float2*)(out + (size_t)(r + 8) * ldo + cc) = v1;
        }
    }
}

// ---------------- host ----------------
extern "C" void kernel_launch(void* const* d_in, const int* in_sizes, int n_in,
                              void* d_out, int out_size) {
    const float* x  = (const float*)d_in[0];
    const float* Wb = (const float*)d_in[1];
    const float* bb = (const float*)d_in[2];
    const float* Wr = (const float*)d_in[3];
    const float* A  = (const float*)d_in[4];
    const float* B  = (const float*)d_in[5];
    float* out = (float*)d_out;

    void *p_xh, *p_wh, *p_ah, *p_bh, *p_ch, *p_H, *p_lg;
    cudaGetSymbolAddress(&p_xh, g_xh); cudaGetSymbolAddress(&p_wh, g_wh);
    cudaGetSymbolAddress(&p_ah, g_ah); cudaGetSymbolAddress(&p_bh, g_bh);
    cudaGetSymbolAddress(&p_ch, g_ch); cudaGetSymbolAddress(&p_H, g_H);
    cudaGetSymbolAddress(&p_lg, g_lg);

    // prep: converts + fused router/x-convert
    tohalf_k<<<(DOUT * DIN / 4) / 256, 256>>>(Wb, (h16*)p_wh, DOUT * DIN / 4);
    tohalf_k<<<(NCAT * DIN / 4) / 256, 256>>>(A, (h16*)p_ah, NCAT * DIN / 4);  // A is [128,4096]
    bcat_k<<<(DOUT * NCAT) / 256, 256>>>(B, (h16*)p_bh);
    cudaFuncSetAttribute(router_splitx_k, cudaFuncAttributeMaxDynamicSharedMemorySize, 131072);
    router_splitx_k<<<TT / 32, 1024, 131072>>>(x, Wr, (float*)p_lg, (h16*)p_xh);

    // H = x @ Acat^T (single-pass fp16). BN=64 -> 128 CTAs.
    constexpr int SM_H = 4 * (BM + 64) * 128 + 1024;
    cudaFuncSetAttribute(gemm_mma<64>, cudaFuncAttributeMaxDynamicSharedMemorySize, SM_H);
    gemm_mma<64><<<dim3(2, TT / BM), 512, SM_H>>>(
        (const h16*)p_xh, (const h16*)p_ah,
        (const h16*)nullptr, (const h16*)nullptr,
        DIN / 64, DIN / 64, DIN, (float*)p_H, nullptr, NCAT);

    combine_k<<<TT, 32>>>((float*)p_lg, (float*)p_H, (h16*)p_ch);

    // out = x @ W^T + C @ Bcat^T + bias  (LoRA rides as 2 extra BK=64 iters)
    constexpr int SM_M = 4 * (BM + 256) * 128 + 1024;
    cudaFuncSetAttribute(gemm_mma<256>, cudaFuncAttributeMaxDynamicSharedMemorySize, SM_M);
    gemm_mma<256><<<dim3(DOUT / 256, TT / BM), 512, SM_M>>>(
        (const h16*)p_xh, (const h16*)p_wh,
        (const h16*)p_ch, (const h16*)p_bh,
        DIN / 64, DIN / 64 + 2, DIN, out, bb, DOUT);
}